// round 1
// baseline (speedup 1.0000x reference)
#include <cuda_runtime.h>
#include <cstdint>

#define BATCH 8
#define LSEQ  1024
#define DM    256
#define DS    16
#define DC    4
#define DI    512
#define DTR   16
#define BL    (BATCH * LSEQ)   // 8192
#define XDBLC (DTR + 2 * DS)   // 48

// ---------------- scratch (single static device buffer; no allocations) ---
// layout (floats):
//  xn    : BL*DM                      =  2,097,152
//  xr[2] : 2 * BL*2*DI                = 16,777,216
//  xsc[2]: 2 * BL*DI                  =  8,388,608
//  xdbl[2]:2 * BL*48                  =    786,432
//  delta[2]:2 * BL*DI                 =  8,388,608
//  y[2]  : 2 * BL*DI                  =  8,388,608
//  cat   : BL*2*DM? -> BL*512        =  4,194,304
static const size_t OFF_XN    = 0;
static const size_t OFF_XR    = OFF_XN    + (size_t)BL * DM;
static const size_t OFF_XSC   = OFF_XR    + (size_t)2 * BL * 2 * DI;
static const size_t OFF_XDBL  = OFF_XSC   + (size_t)2 * BL * DI;
static const size_t OFF_DELTA = OFF_XDBL  + (size_t)2 * BL * XDBLC;
static const size_t OFF_Y     = OFF_DELTA + (size_t)2 * BL * DI;
static const size_t OFF_CAT   = OFF_Y     + (size_t)2 * BL * DI;
static const size_t TOTAL_F   = OFF_CAT   + (size_t)BL * 512;

__device__ float g_buf[TOTAL_F];

// ---------------- LayerNorm: one block per token ---------------------------
__global__ void ln_kernel(const float* __restrict__ x,
                          const float* __restrict__ g,
                          const float* __restrict__ b,
                          float* __restrict__ xn)
{
    int m = blockIdx.x;
    int t = threadIdx.x;            // 0..255
    float v = x[(size_t)m * DM + t];
    float s = v, s2 = v * v;
    #pragma unroll
    for (int o = 16; o; o >>= 1) {
        s  += __shfl_xor_sync(0xffffffffu, s,  o);
        s2 += __shfl_xor_sync(0xffffffffu, s2, o);
    }
    __shared__ float ws[8], ws2[8];
    int w = t >> 5, l = t & 31;
    if (l == 0) { ws[w] = s; ws2[w] = s2; }
    __syncthreads();
    float S = 0.f, S2 = 0.f;
    #pragma unroll
    for (int i = 0; i < 8; i++) { S += ws[i]; S2 += ws2[i]; }
    float mu  = S * (1.0f / DM);
    float var = S2 * (1.0f / DM) - mu * mu;
    float r = rsqrtf(var + 1e-5f);
    xn[(size_t)m * DM + t] = (v - mu) * r * g[t] + b[t];
}

// ---------------- generic tiled fp32 GEMM ---------------------------------
// C[cr, coff+c] = sum_k A[amap(m), k] * W[k, c]   (row-major; ldw == N stride)
// BM=BN=128, BK=16, 256 threads, 8x8 per thread.
// flipA/flipC: row index XOR 1023 (time-flip within each batch of L=1024).
// epi: 0 = none; 1 = softplus(v + bias[c]); 2 = v + bias[c] + resid[r*N+c].
__global__ __launch_bounds__(256, 2)
void gemm_k(const float* __restrict__ A, int lda, int flipA,
            const float* __restrict__ W, int ldw,
            float* __restrict__ C, int ldc, int flipC, int coff,
            int N, int K, int epi,
            const float* __restrict__ bias,
            const float* __restrict__ resid)
{
    __shared__ float As[16][128];
    __shared__ float Bs[16][128];
    const int tid = threadIdx.x;
    const int m0 = blockIdx.x * 128;
    const int n0 = blockIdx.y * 128;
    const int ty = tid >> 4, tx = tid & 15;

    // A loading: each thread loads 8 floats (2x float4) of one row
    int arow  = tid >> 1;              // 0..127
    int akoff = (tid & 1) * 8;         // 0 or 8
    int am = m0 + arow;
    if (flipA) am ^= (LSEQ - 1);
    const float* Ap = A + (size_t)am * lda + akoff;

    // B loading: each thread loads 8 floats of one k-row
    int brow = tid >> 4;               // 0..15
    int bcol = (tid & 15) * 8;         // 0..120
    const float* Wp = W + (size_t)brow * ldw + n0 + bcol;
    const bool fullN = (n0 + 128 <= N);

    float acc[8][8];
    #pragma unroll
    for (int i = 0; i < 8; i++)
        #pragma unroll
        for (int j = 0; j < 8; j++) acc[i][j] = 0.f;

    for (int kk = 0; kk < K; kk += 16) {
        float4 a0 = *(const float4*)(Ap);
        float4 a1 = *(const float4*)(Ap + 4);
        As[akoff + 0][arow] = a0.x; As[akoff + 1][arow] = a0.y;
        As[akoff + 2][arow] = a0.z; As[akoff + 3][arow] = a0.w;
        As[akoff + 4][arow] = a1.x; As[akoff + 5][arow] = a1.y;
        As[akoff + 6][arow] = a1.z; As[akoff + 7][arow] = a1.w;
        if (fullN) {
            *(float4*)&Bs[brow][bcol]     = *(const float4*)(Wp);
            *(float4*)&Bs[brow][bcol + 4] = *(const float4*)(Wp + 4);
        } else {
            #pragma unroll
            for (int j = 0; j < 8; j++)
                Bs[brow][bcol + j] = (n0 + bcol + j < N) ? Wp[j] : 0.f;
        }
        __syncthreads();
        #pragma unroll
        for (int k = 0; k < 16; k++) {
            float a[8], b[8];
            *(float4*)&a[0] = *(const float4*)&As[k][ty * 8];
            *(float4*)&a[4] = *(const float4*)&As[k][ty * 8 + 4];
            *(float4*)&b[0] = *(const float4*)&Bs[k][tx * 8];
            *(float4*)&b[4] = *(const float4*)&Bs[k][tx * 8 + 4];
            #pragma unroll
            for (int i = 0; i < 8; i++)
                #pragma unroll
                for (int j = 0; j < 8; j++)
                    acc[i][j] = fmaf(a[i], b[j], acc[i][j]);
        }
        __syncthreads();
        Ap += 16;
        Wp += (size_t)16 * ldw;
    }

    #pragma unroll
    for (int i = 0; i < 8; i++) {
        int r  = m0 + ty * 8 + i;
        int cr = flipC ? (r ^ (LSEQ - 1)) : r;
        #pragma unroll
        for (int j = 0; j < 8; j++) {
            int c = n0 + tx * 8 + j;
            if (c < N) {
                float v = acc[i][j];
                if (epi == 1) {
                    v += bias[c];
                    v = (v > 20.f) ? v : log1pf(__expf(v));
                } else if (epi == 2) {
                    v += bias[c] + resid[(size_t)r * N + c];
                }
                C[(size_t)cr * ldc + coff + c] = v;
            }
        }
    }
}

// ---------------- causal depthwise conv (DC=4) + bias + SiLU ---------------
// input: xs part of xr (cols 0..DI-1 of row stride 2*DI); output xsc (stride DI)
__global__ void conv_silu_kernel(const float* __restrict__ xr,
                                 const float* __restrict__ cw,
                                 const float* __restrict__ cb,
                                 float* __restrict__ xsc)
{
    int idx = blockIdx.x * 256 + threadIdx.x;     // BL*DI threads
    int row = idx >> 9;                            // token index
    int c   = idx & (DI - 1);
    int tau = row & (LSEQ - 1);
    const float* p = xr + (size_t)row * (2 * DI) + c;
    float w0 = cw[c * 4 + 0], w1 = cw[c * 4 + 1], w2 = cw[c * 4 + 2], w3 = cw[c * 4 + 3];
    float acc = cb[c];
    if (tau >= 3) acc = fmaf(p[-3 * 2 * DI], w0, acc);
    if (tau >= 2) acc = fmaf(p[-2 * 2 * DI], w1, acc);
    if (tau >= 1) acc = fmaf(p[-1 * 2 * DI], w2, acc);
    acc = fmaf(p[0], w3, acc);
    float sv = acc / (1.f + __expf(-acc));
    xsc[(size_t)row * DI + c] = sv;
}

// ---------------- selective scan + D*x + silu(res) gate --------------------
// thread = one (b, d) chain; 16 states in registers; B/C staged via shared.
__global__ __launch_bounds__(128)
void scan_kernel(const float* __restrict__ xdbl,
                 const float* __restrict__ delta,
                 const float* __restrict__ xsc,
                 const float* __restrict__ xr,
                 const float* __restrict__ ALog,
                 const float* __restrict__ Dp,
                 float* __restrict__ y)
{
    __shared__ float sBC[64][32];
    int b   = blockIdx.y;
    int d   = blockIdx.x * 128 + threadIdx.x;
    int tid = threadIdx.x;

    float a[16];
    #pragma unroll
    for (int n = 0; n < 16; n++) a[n] = -__expf(ALog[d * 16 + n]);
    float Dv = Dp[d];
    float h[16];
    #pragma unroll
    for (int n = 0; n < 16; n++) h[n] = 0.f;

    int base = b * LSEQ;
    for (int t0 = 0; t0 < LSEQ; t0 += 64) {
        __syncthreads();
        for (int i = tid; i < 64 * 32; i += 128) {
            int tt = i >> 5, cc = i & 31;
            sBC[tt][cc] = xdbl[(size_t)(base + t0 + tt) * XDBLC + DTR + cc];
        }
        __syncthreads();
        for (int tc = 0; tc < 64; tc++) {
            size_t row = (size_t)(base + t0 + tc);
            float dlt = delta[row * DI + d];
            float xv  = xsc[row * DI + d];
            float dx  = dlt * xv;
            float yv  = 0.f;
            #pragma unroll
            for (int n = 0; n < 16; n++) {
                float dA = __expf(dlt * a[n]);
                h[n] = fmaf(dA, h[n], dx * sBC[tc][n]);
                yv   = fmaf(h[n], sBC[tc][16 + n], yv);
            }
            float res  = xr[row * (2 * DI) + DI + d];
            float sres = res / (1.f + __expf(-res));
            y[row * DI + d] = (yv + Dv * xv) * sres;
        }
    }
}

// ---------------- launcher -------------------------------------------------
extern "C" void kernel_launch(void* const* d_in, const int* in_sizes, int n_in,
                              void* d_out, int out_size)
{
    const float* x      = (const float*)d_in[0];
    const float* norm_g = (const float*)d_in[1];
    const float* norm_b = (const float*)d_in[2];
    const float* inW[2]   = {(const float*)d_in[3],  (const float*)d_in[12]};
    const float* convW[2] = {(const float*)d_in[4],  (const float*)d_in[13]};
    const float* convB[2] = {(const float*)d_in[5],  (const float*)d_in[14]};
    const float* xW[2]    = {(const float*)d_in[6],  (const float*)d_in[15]};
    const float* dtW[2]   = {(const float*)d_in[7],  (const float*)d_in[16]};
    const float* dtB[2]   = {(const float*)d_in[8],  (const float*)d_in[17]};
    const float* ALog[2]  = {(const float*)d_in[9],  (const float*)d_in[18]};
    const float* Dp[2]    = {(const float*)d_in[10], (const float*)d_in[19]};
    const float* outW[2]  = {(const float*)d_in[11], (const float*)d_in[20]};
    const float* fusW = (const float*)d_in[21];
    const float* fusB = (const float*)d_in[22];
    float* out = (float*)d_out;

    float* base = nullptr;
    cudaGetSymbolAddress((void**)&base, g_buf);
    float* xn      = base + OFF_XN;
    float* xr_[2]    = {base + OFF_XR,    base + OFF_XR    + (size_t)BL * 2 * DI};
    float* xsc_[2]   = {base + OFF_XSC,   base + OFF_XSC   + (size_t)BL * DI};
    float* xdbl_[2]  = {base + OFF_XDBL,  base + OFF_XDBL  + (size_t)BL * XDBLC};
    float* delta_[2] = {base + OFF_DELTA, base + OFF_DELTA + (size_t)BL * DI};
    float* y_[2]     = {base + OFF_Y,     base + OFF_Y     + (size_t)BL * DI};
    float* cat_      = base + OFF_CAT;

    // 1) LayerNorm
    ln_kernel<<<BL, 256>>>(x, norm_g, norm_b, xn);

    for (int m = 0; m < 2; m++) {
        // 2) in_proj  (flip A rows for backward direction)
        gemm_k<<<dim3(BL / 128, 1024 / 128), 256>>>(
            xn, DM, m, inW[m], 2 * DI,
            xr_[m], 2 * DI, 0, 0, 2 * DI, DM, 0, nullptr, nullptr);
        // 3) causal dw-conv + silu
        conv_silu_kernel<<<(BL * DI) / 256, 256>>>(xr_[m], convW[m], convB[m], xsc_[m]);
        // 4) x_proj -> [dlt | B | C]
        gemm_k<<<dim3(BL / 128, 1), 256>>>(
            xsc_[m], DI, 0, xW[m], XDBLC,
            xdbl_[m], XDBLC, 0, 0, XDBLC, DI, 0, nullptr, nullptr);
        // 5) delta = softplus(dlt @ dtW + dtB)
        gemm_k<<<dim3(BL / 128, DI / 128), 256>>>(
            xdbl_[m], XDBLC, 0, dtW[m], DI,
            delta_[m], DI, 0, 0, DI, DTR, 1, dtB[m], nullptr);
        // 6) scan + D*x + silu(res) gate
        scan_kernel<<<dim3(DI / 128, BATCH), 128>>>(
            xdbl_[m], delta_[m], xsc_[m], xr_[m], ALog[m], Dp[m], y_[m]);
        // 7) out_proj into concat buffer (unflip rows for backward)
        gemm_k<<<dim3(BL / 128, DM / 128), 256>>>(
            y_[m], DI, 0, outW[m], DM,
            cat_, 512, m /*flipC*/, m * DM, DM, DI, 0, nullptr, nullptr);
    }

    // 8) fuse: out = x + cat @ fusW + fusB
    gemm_k<<<dim3(BL / 128, DM / 128), 256>>>(
        cat_, 512, 0, fusW, DM,
        out, DM, 0, 0, DM, 512, 2, fusB, x);
}

// round 2
// speedup vs baseline: 2.2764x; 2.2764x over previous
#include <cuda_runtime.h>
#include <cstdint>

#define BATCH 8
#define LSEQ  1024
#define DM    256
#define DS    16
#define DC    4
#define DI    512
#define DTR   16
#define BL    (BATCH * LSEQ)   // 8192
#define XDBLC (DTR + 2 * DS)   // 48

// ---------------- scratch (single static device buffer; no allocations) ---
static const size_t OFF_XN    = 0;
static const size_t OFF_XR    = OFF_XN    + (size_t)BL * DM;
static const size_t OFF_XSC   = OFF_XR    + (size_t)2 * BL * 2 * DI;
static const size_t OFF_XDBL  = OFF_XSC   + (size_t)2 * BL * DI;
static const size_t OFF_DELTA = OFF_XDBL  + (size_t)2 * BL * XDBLC;
static const size_t OFF_Y     = OFF_DELTA + (size_t)2 * BL * DI;
static const size_t OFF_CAT   = OFF_Y     + (size_t)2 * BL * DI;
static const size_t TOTAL_F   = OFF_CAT   + (size_t)BL * 512;

__device__ float g_buf[TOTAL_F];

// ---------------- LayerNorm: one block per token ---------------------------
__global__ void ln_kernel(const float* __restrict__ x,
                          const float* __restrict__ g,
                          const float* __restrict__ b,
                          float* __restrict__ xn)
{
    int m = blockIdx.x;
    int t = threadIdx.x;            // 0..255
    float v = x[(size_t)m * DM + t];
    float s = v, s2 = v * v;
    #pragma unroll
    for (int o = 16; o; o >>= 1) {
        s  += __shfl_xor_sync(0xffffffffu, s,  o);
        s2 += __shfl_xor_sync(0xffffffffu, s2, o);
    }
    __shared__ float ws[8], ws2[8];
    int w = t >> 5, l = t & 31;
    if (l == 0) { ws[w] = s; ws2[w] = s2; }
    __syncthreads();
    float S = 0.f, S2 = 0.f;
    #pragma unroll
    for (int i = 0; i < 8; i++) { S += ws[i]; S2 += ws2[i]; }
    float mu  = S * (1.0f / DM);
    float var = S2 * (1.0f / DM) - mu * mu;
    float r = rsqrtf(var + 1e-5f);
    xn[(size_t)m * DM + t] = (v - mu) * r * g[t] + b[t];
}

// ---------------- tf32 tensor-core GEMM ------------------------------------
// C[cr, coff*z + c] = sum_k A[amap(m), k] * W[k, c]
// 128x128x32 tiles, 256 threads (8 warps, 2x4), warp tile 64x32.
// blockIdx.z selects direction (pointer set 0/1).
// flipA/flipC: applied when z==1 (time flip, row XOR 1023).
// epi: 0 none; 1 softplus(v + bias[c]); 2 v + bias[c] + resid[r*N+c].

#define AS_STRIDE 36
#define BS_STRIDE 136
#define SMEM_BYTES ((2*128*AS_STRIDE + 2*32*BS_STRIDE) * 4)

__device__ __forceinline__ unsigned cvta_s(const void* p) {
    return (unsigned)__cvta_generic_to_shared(p);
}
__device__ __forceinline__ void cp16(unsigned dst, const void* src, int srcbytes) {
    asm volatile("cp.async.cg.shared.global [%0], [%1], 16, %2;\n"
                 :: "r"(dst), "l"(src), "r"(srcbytes));
}
__device__ __forceinline__ unsigned f2tf32(float x) {
    unsigned r;
    asm("cvt.rna.tf32.f32 %0, %1;" : "=r"(r) : "f"(x));
    return r;
}

__global__ __launch_bounds__(256)
void mma_gemm(const float* __restrict__ A0, const float* __restrict__ A1, int lda, int flipA,
              const float* __restrict__ W0, const float* __restrict__ W1, int ldw,
              float* __restrict__ C0, float* __restrict__ C1, int ldc, int flipC, int coffz,
              int N, int K, int epi,
              const float* __restrict__ bias0, const float* __restrict__ bias1,
              const float* __restrict__ resid)
{
    extern __shared__ float smem[];
    float* As = smem;                          // [2][128][AS_STRIDE]
    float* Bs = smem + 2 * 128 * AS_STRIDE;    // [2][32][BS_STRIDE]

    const int z = blockIdx.z;
    const float* A = z ? A1 : A0;
    const float* W = z ? W1 : W0;
    float*       C = z ? C1 : C0;
    const float* bias = z ? bias1 : bias0;
    const int fA = (flipA && z);
    const int fC = (flipC && z);
    const int coff = coffz * z;

    const int tid = threadIdx.x;
    const int m0 = blockIdx.x * 128;
    const int n0 = blockIdx.y * 128;

    // A load mapping: thread -> row tid>>1, 16 floats at col (tid&1)*16
    const int ar  = tid >> 1;
    const int akc = (tid & 1) * 16;
    int gm = m0 + ar;
    if (fA) gm ^= (LSEQ - 1);
    const float* Agp = A + (size_t)gm * lda;

    // B load mapping: thread -> row tid>>3, 16 floats at col (tid&7)*16
    const int bkr = tid >> 3;
    const int bnc = (tid & 7) * 16;

    const int wid = tid >> 5, lane = tid & 31;
    const int wm = wid & 1, wn = wid >> 1;       // warp tile origin (wm*64, wn*32)
    const int lr = lane >> 2, lc = lane & 3;

    float acc[4][4][4];
    #pragma unroll
    for (int mi = 0; mi < 4; mi++)
        #pragma unroll
        for (int ni = 0; ni < 4; ni++)
            #pragma unroll
            for (int q = 0; q < 4; q++) acc[mi][ni][q] = 0.f;

    const int nk = (K + 31) >> 5;

    // ---- tile loaders ----
    auto loadA = [&](int kk, int buf) {
        float* dst = As + buf * (128 * AS_STRIDE) + ar * AS_STRIDE + akc;
        #pragma unroll
        for (int j = 0; j < 4; j++) {
            int kg = kk + akc + j * 4;
            int sb = (kg < K) ? 16 : 0;
            cp16(cvta_s(dst + j * 4), Agp + (sb ? kg : 0), sb);
        }
    };
    auto loadB = [&](int kk, int buf) {
        int kg = kk + bkr;
        int inK = (kg < K);
        const float* srow = W + (size_t)(inK ? kg : 0) * ldw;
        float* dst = Bs + buf * (32 * BS_STRIDE) + bkr * BS_STRIDE + bnc;
        #pragma unroll
        for (int j = 0; j < 4; j++) {
            int gn = n0 + bnc + j * 4;
            int sb = (inK && gn < N) ? 16 : 0;
            cp16(cvta_s(dst + j * 4), srow + (sb ? gn : 0), sb);
        }
    };

    loadA(0, 0); loadB(0, 0);
    asm volatile("cp.async.commit_group;\n");

    for (int t = 0; t < nk; t++) {
        if (t + 1 < nk) {
            loadA((t + 1) << 5, (t + 1) & 1);
            loadB((t + 1) << 5, (t + 1) & 1);
            asm volatile("cp.async.commit_group;\n");
            asm volatile("cp.async.wait_group 1;\n");
        } else {
            asm volatile("cp.async.wait_group 0;\n");
        }
        __syncthreads();

        const int buf = t & 1;
        const float* AsB = As + buf * (128 * AS_STRIDE);
        const float* BsB = Bs + buf * (32 * BS_STRIDE);

        #pragma unroll
        for (int s = 0; s < 4; s++) {
            unsigned af[4][4], bf[4][2];
            #pragma unroll
            for (int mi = 0; mi < 4; mi++) {
                const float* p = AsB + (wm * 64 + mi * 16 + lr) * AS_STRIDE + s * 8 + lc;
                af[mi][0] = f2tf32(p[0]);
                af[mi][1] = f2tf32(p[8 * AS_STRIDE]);
                af[mi][2] = f2tf32(p[4]);
                af[mi][3] = f2tf32(p[8 * AS_STRIDE + 4]);
            }
            #pragma unroll
            for (int ni = 0; ni < 4; ni++) {
                const float* p = BsB + (s * 8 + lc) * BS_STRIDE + wn * 32 + ni * 8 + lr;
                bf[ni][0] = f2tf32(p[0]);
                bf[ni][1] = f2tf32(p[4 * BS_STRIDE]);
            }
            #pragma unroll
            for (int mi = 0; mi < 4; mi++)
                #pragma unroll
                for (int ni = 0; ni < 4; ni++) {
                    asm volatile(
                        "mma.sync.aligned.m16n8k8.row.col.f32.tf32.tf32.f32 "
                        "{%0,%1,%2,%3},{%4,%5,%6,%7},{%8,%9},{%0,%1,%2,%3};\n"
                        : "+f"(acc[mi][ni][0]), "+f"(acc[mi][ni][1]),
                          "+f"(acc[mi][ni][2]), "+f"(acc[mi][ni][3])
                        : "r"(af[mi][0]), "r"(af[mi][1]), "r"(af[mi][2]), "r"(af[mi][3]),
                          "r"(bf[ni][0]), "r"(bf[ni][1]));
                }
        }
        __syncthreads();
    }

    // ---- epilogue ----
    #pragma unroll
    for (int mi = 0; mi < 4; mi++) {
        int r0r = m0 + wm * 64 + mi * 16 + lr;
        #pragma unroll
        for (int ni = 0; ni < 4; ni++) {
            int cb = n0 + wn * 32 + ni * 8 + 2 * lc;
            #pragma unroll
            for (int q = 0; q < 4; q++) {
                int r = r0r + (q >> 1) * 8;
                int c = cb + (q & 1);
                if (c < N) {
                    float v = acc[mi][ni][q];
                    if (epi == 1) {
                        v += bias[c];
                        v = (v > 20.f) ? v : log1pf(__expf(v));
                    } else if (epi == 2) {
                        v += bias[c] + resid[(size_t)r * N + c];
                    }
                    int cr = fC ? (r ^ (LSEQ - 1)) : r;
                    C[(size_t)cr * ldc + coff + c] = v;
                }
            }
        }
    }
}

// ---------------- causal depthwise conv (DC=4) + bias + SiLU ---------------
__global__ void conv_silu_kernel(const float* __restrict__ xr0, const float* __restrict__ xr1,
                                 const float* __restrict__ cw0, const float* __restrict__ cw1,
                                 const float* __restrict__ cb0, const float* __restrict__ cb1,
                                 float* __restrict__ xsc0, float* __restrict__ xsc1)
{
    int dir = blockIdx.y;
    const float* xr = dir ? xr1 : xr0;
    const float* cw = dir ? cw1 : cw0;
    const float* cb = dir ? cb1 : cb0;
    float* xsc = dir ? xsc1 : xsc0;

    int idx = blockIdx.x * 256 + threadIdx.x;     // BL*DI threads
    int row = idx >> 9;                            // token index
    int c   = idx & (DI - 1);
    int tau = row & (LSEQ - 1);
    const float* p = xr + (size_t)row * (2 * DI) + c;
    float w0 = cw[c * 4 + 0], w1 = cw[c * 4 + 1], w2 = cw[c * 4 + 2], w3 = cw[c * 4 + 3];
    float acc = cb[c];
    if (tau >= 3) acc = fmaf(p[-3 * 2 * DI], w0, acc);
    if (tau >= 2) acc = fmaf(p[-2 * 2 * DI], w1, acc);
    if (tau >= 1) acc = fmaf(p[-1 * 2 * DI], w2, acc);
    acc = fmaf(p[0], w3, acc);
    float sv = acc / (1.f + __expf(-acc));
    xsc[(size_t)row * DI + c] = sv;
}

// ---------------- selective scan + D*x + silu(res) gate --------------------
__global__ __launch_bounds__(128)
void scan_kernel(const float* __restrict__ xdbl0, const float* __restrict__ xdbl1,
                 const float* __restrict__ delta0, const float* __restrict__ delta1,
                 const float* __restrict__ xsc0, const float* __restrict__ xsc1,
                 const float* __restrict__ xr0, const float* __restrict__ xr1,
                 const float* __restrict__ ALog0, const float* __restrict__ ALog1,
                 const float* __restrict__ Dp0, const float* __restrict__ Dp1,
                 float* __restrict__ y0, float* __restrict__ y1)
{
    int dir = blockIdx.z;
    const float* xdbl  = dir ? xdbl1  : xdbl0;
    const float* delta = dir ? delta1 : delta0;
    const float* xsc   = dir ? xsc1   : xsc0;
    const float* xr    = dir ? xr1    : xr0;
    const float* ALog  = dir ? ALog1  : ALog0;
    const float* Dp    = dir ? Dp1    : Dp0;
    float* y           = dir ? y1     : y0;

    __shared__ float sBC[64][32];
    int b   = blockIdx.y;
    int d   = blockIdx.x * 128 + threadIdx.x;
    int tid = threadIdx.x;

    float a[16];
    #pragma unroll
    for (int n = 0; n < 16; n++) a[n] = -__expf(ALog[d * 16 + n]);
    float Dv = Dp[d];
    float h[16];
    #pragma unroll
    for (int n = 0; n < 16; n++) h[n] = 0.f;

    int base = b * LSEQ;
    for (int t0 = 0; t0 < LSEQ; t0 += 64) {
        __syncthreads();
        for (int i = tid; i < 64 * 32; i += 128) {
            int tt = i >> 5, cc = i & 31;
            sBC[tt][cc] = xdbl[(size_t)(base + t0 + tt) * XDBLC + DTR + cc];
        }
        __syncthreads();
        for (int tc = 0; tc < 64; tc++) {
            size_t row = (size_t)(base + t0 + tc);
            float dlt = delta[row * DI + d];
            float xv  = xsc[row * DI + d];
            float dx  = dlt * xv;
            float yv  = 0.f;
            #pragma unroll
            for (int n = 0; n < 16; n++) {
                float dA = __expf(dlt * a[n]);
                h[n] = fmaf(dA, h[n], dx * sBC[tc][n]);
                yv   = fmaf(h[n], sBC[tc][16 + n], yv);
            }
            float res  = xr[row * (2 * DI) + DI + d];
            float sres = res / (1.f + __expf(-res));
            y[row * DI + d] = (yv + Dv * xv) * sres;
        }
    }
}

// ---------------- launcher -------------------------------------------------
extern "C" void kernel_launch(void* const* d_in, const int* in_sizes, int n_in,
                              void* d_out, int out_size)
{
    const float* x      = (const float*)d_in[0];
    const float* norm_g = (const float*)d_in[1];
    const float* norm_b = (const float*)d_in[2];
    const float* inW[2]   = {(const float*)d_in[3],  (const float*)d_in[12]};
    const float* convW[2] = {(const float*)d_in[4],  (const float*)d_in[13]};
    const float* convB[2] = {(const float*)d_in[5],  (const float*)d_in[14]};
    const float* xW[2]    = {(const float*)d_in[6],  (const float*)d_in[15]};
    const float* dtW[2]   = {(const float*)d_in[7],  (const float*)d_in[16]};
    const float* dtB[2]   = {(const float*)d_in[8],  (const float*)d_in[17]};
    const float* ALog[2]  = {(const float*)d_in[9],  (const float*)d_in[18]};
    const float* Dp[2]    = {(const float*)d_in[10], (const float*)d_in[19]};
    const float* outW[2]  = {(const float*)d_in[11], (const float*)d_in[20]};
    const float* fusW = (const float*)d_in[21];
    const float* fusB = (const float*)d_in[22];
    float* out = (float*)d_out;

    float* base = nullptr;
    cudaGetSymbolAddress((void**)&base, g_buf);
    float* xn        = base + OFF_XN;
    float* xr_[2]    = {base + OFF_XR,    base + OFF_XR    + (size_t)BL * 2 * DI};
    float* xsc_[2]   = {base + OFF_XSC,   base + OFF_XSC   + (size_t)BL * DI};
    float* xdbl_[2]  = {base + OFF_XDBL,  base + OFF_XDBL  + (size_t)BL * XDBLC};
    float* delta_[2] = {base + OFF_DELTA, base + OFF_DELTA + (size_t)BL * DI};
    float* y_[2]     = {base + OFF_Y,     base + OFF_Y     + (size_t)BL * DI};
    float* cat_      = base + OFF_CAT;

    static bool attr_set = false;
    if (!attr_set) {
        cudaFuncSetAttribute(mma_gemm, cudaFuncAttributeMaxDynamicSharedMemorySize, SMEM_BYTES);
        attr_set = true;
    }

    // 1) LayerNorm
    ln_kernel<<<BL, 256>>>(x, norm_g, norm_b, xn);

    // 2) in_proj, both dirs (flip A rows for backward)
    mma_gemm<<<dim3(BL / 128, 8, 2), 256, SMEM_BYTES>>>(
        xn, xn, DM, 1,
        inW[0], inW[1], 2 * DI,
        xr_[0], xr_[1], 2 * DI, 0, 0,
        2 * DI, DM, 0, nullptr, nullptr, nullptr);

    // 3) causal dw-conv + silu, both dirs
    conv_silu_kernel<<<dim3((BL * DI) / 256, 2), 256>>>(
        xr_[0], xr_[1], convW[0], convW[1], convB[0], convB[1], xsc_[0], xsc_[1]);

    // 4) x_proj -> [dlt | B | C], both dirs
    mma_gemm<<<dim3(BL / 128, 1, 2), 256, SMEM_BYTES>>>(
        xsc_[0], xsc_[1], DI, 0,
        xW[0], xW[1], XDBLC,
        xdbl_[0], xdbl_[1], XDBLC, 0, 0,
        XDBLC, DI, 0, nullptr, nullptr, nullptr);

    // 5) delta = softplus(dlt @ dtW + dtB), both dirs
    mma_gemm<<<dim3(BL / 128, 4, 2), 256, SMEM_BYTES>>>(
        xdbl_[0], xdbl_[1], XDBLC, 0,
        dtW[0], dtW[1], DI,
        delta_[0], delta_[1], DI, 0, 0,
        DI, DTR, 1, dtB[0], dtB[1], nullptr);

    // 6) scan + D*x + silu(res) gate, both dirs
    scan_kernel<<<dim3(DI / 128, BATCH, 2), 128>>>(
        xdbl_[0], xdbl_[1], delta_[0], delta_[1], xsc_[0], xsc_[1],
        xr_[0], xr_[1], ALog[0], ALog[1], Dp[0], Dp[1], y_[0], y_[1]);

    // 7) out_proj into concat buffer (unflip rows for backward)
    mma_gemm<<<dim3(BL / 128, 2, 2), 256, SMEM_BYTES>>>(
        y_[0], y_[1], DI, 0,
        outW[0], outW[1], DM,
        cat_, cat_, 512, 1, DM,
        DM, DI, 0, nullptr, nullptr, nullptr);

    // 8) fuse: out = x + cat @ fusW + fusB
    mma_gemm<<<dim3(BL / 128, 2, 1), 256, SMEM_BYTES>>>(
        cat_, cat_, 512, 0,
        fusW, fusW, DM,
        out, out, DM, 0, 0,
        DM, 512, 2, fusB, fusB, x);
}

// round 3
// speedup vs baseline: 5.2915x; 2.3245x over previous
#include <cuda_runtime.h>
#include <cstdint>

#define BATCH 8
#define LSEQ  1024
#define DM    256
#define DS    16
#define DC    4
#define DI    512
#define DTR   16
#define BL    (BATCH * LSEQ)   // 8192
#define XDBLC (DTR + 2 * DS)   // 48
#define CH    128
#define NCH   (LSEQ / CH)      // 8

// ---------------- scratch (single static device buffer; no allocations) ---
static const size_t OFF_XN    = 0;
static const size_t OFF_XR    = OFF_XN    + (size_t)BL * DM;
static const size_t OFF_XSC   = OFF_XR    + (size_t)2 * BL * 2 * DI;
static const size_t OFF_XDBL  = OFF_XSC   + (size_t)2 * BL * DI;
static const size_t OFF_DELTA = OFF_XDBL  + (size_t)2 * BL * XDBLC;
static const size_t OFF_Y     = OFF_DELTA + (size_t)2 * BL * DI;
static const size_t OFF_CAT   = OFF_Y     + (size_t)2 * BL * DI;
static const size_t OFF_HF    = OFF_CAT   + (size_t)BL * 512;
static const size_t OFF_DS    = OFF_HF    + (size_t)2 * 8 * NCH * 16 * 512;
static const size_t TOTAL_F   = OFF_DS    + (size_t)2 * 8 * NCH * 512;

__device__ float g_buf[TOTAL_F];

// ---------------- LayerNorm ------------------------------------------------
__global__ void ln_kernel(const float* __restrict__ x,
                          const float* __restrict__ g,
                          const float* __restrict__ b,
                          float* __restrict__ xn)
{
    int m = blockIdx.x;
    int t = threadIdx.x;
    float v = x[(size_t)m * DM + t];
    float s = v, s2 = v * v;
    #pragma unroll
    for (int o = 16; o; o >>= 1) {
        s  += __shfl_xor_sync(0xffffffffu, s,  o);
        s2 += __shfl_xor_sync(0xffffffffu, s2, o);
    }
    __shared__ float ws[8], ws2[8];
    int w = t >> 5, l = t & 31;
    if (l == 0) { ws[w] = s; ws2[w] = s2; }
    __syncthreads();
    float S = 0.f, S2 = 0.f;
    #pragma unroll
    for (int i = 0; i < 8; i++) { S += ws[i]; S2 += ws2[i]; }
    float mu  = S * (1.0f / DM);
    float var = S2 * (1.0f / DM) - mu * mu;
    float r = rsqrtf(var + 1e-5f);
    xn[(size_t)m * DM + t] = (v - mu) * r * g[t] + b[t];
}

// ---------------- tf32 tensor-core GEMM ------------------------------------
#define AS_STRIDE 36
#define BS_STRIDE 136
#define SMEM_BYTES ((2*128*AS_STRIDE + 2*32*BS_STRIDE) * 4)

__device__ __forceinline__ unsigned cvta_s(const void* p) {
    return (unsigned)__cvta_generic_to_shared(p);
}
__device__ __forceinline__ void cp16(unsigned dst, const void* src, int srcbytes) {
    asm volatile("cp.async.cg.shared.global [%0], [%1], 16, %2;\n"
                 :: "r"(dst), "l"(src), "r"(srcbytes));
}
__device__ __forceinline__ unsigned f2tf32(float x) {
    unsigned r;
    asm("cvt.rna.tf32.f32 %0, %1;" : "=r"(r) : "f"(x));
    return r;
}

__global__ __launch_bounds__(256)
void mma_gemm(const float* __restrict__ A0, const float* __restrict__ A1, int lda, int flipA,
              const float* __restrict__ W0, const float* __restrict__ W1, int ldw,
              float* __restrict__ C0, float* __restrict__ C1, int ldc, int flipC, int coffz,
              int N, int K, int epi,
              const float* __restrict__ bias0, const float* __restrict__ bias1,
              const float* __restrict__ resid)
{
    extern __shared__ float smem[];
    float* As = smem;
    float* Bs = smem + 2 * 128 * AS_STRIDE;

    const int z = blockIdx.z;
    const float* A = z ? A1 : A0;
    const float* W = z ? W1 : W0;
    float*       C = z ? C1 : C0;
    const float* bias = z ? bias1 : bias0;
    const int fA = (flipA && z);
    const int fC = (flipC && z);
    const int coff = coffz * z;

    const int tid = threadIdx.x;
    const int m0 = blockIdx.x * 128;
    const int n0 = blockIdx.y * 128;

    const int ar  = tid >> 1;
    const int akc = (tid & 1) * 16;
    int gm = m0 + ar;
    if (fA) gm ^= (LSEQ - 1);
    const float* Agp = A + (size_t)gm * lda;

    const int bkr = tid >> 3;
    const int bnc = (tid & 7) * 16;

    const int wid = tid >> 5, lane = tid & 31;
    const int wm = wid & 1, wn = wid >> 1;
    const int lr = lane >> 2, lc = lane & 3;

    float acc[4][4][4];
    #pragma unroll
    for (int mi = 0; mi < 4; mi++)
        #pragma unroll
        for (int ni = 0; ni < 4; ni++)
            #pragma unroll
            for (int q = 0; q < 4; q++) acc[mi][ni][q] = 0.f;

    const int nk = (K + 31) >> 5;

    auto loadA = [&](int kk, int buf) {
        float* dst = As + buf * (128 * AS_STRIDE) + ar * AS_STRIDE + akc;
        #pragma unroll
        for (int j = 0; j < 4; j++) {
            int kg = kk + akc + j * 4;
            int sb = (kg < K) ? 16 : 0;
            cp16(cvta_s(dst + j * 4), Agp + (sb ? kg : 0), sb);
        }
    };
    auto loadB = [&](int kk, int buf) {
        int kg = kk + bkr;
        int inK = (kg < K);
        const float* srow = W + (size_t)(inK ? kg : 0) * ldw;
        float* dst = Bs + buf * (32 * BS_STRIDE) + bkr * BS_STRIDE + bnc;
        #pragma unroll
        for (int j = 0; j < 4; j++) {
            int gn = n0 + bnc + j * 4;
            int sb = (inK && gn < N) ? 16 : 0;
            cp16(cvta_s(dst + j * 4), srow + (sb ? gn : 0), sb);
        }
    };

    loadA(0, 0); loadB(0, 0);
    asm volatile("cp.async.commit_group;\n");

    for (int t = 0; t < nk; t++) {
        if (t + 1 < nk) {
            loadA((t + 1) << 5, (t + 1) & 1);
            loadB((t + 1) << 5, (t + 1) & 1);
            asm volatile("cp.async.commit_group;\n");
            asm volatile("cp.async.wait_group 1;\n");
        } else {
            asm volatile("cp.async.wait_group 0;\n");
        }
        __syncthreads();

        const int buf = t & 1;
        const float* AsB = As + buf * (128 * AS_STRIDE);
        const float* BsB = Bs + buf * (32 * BS_STRIDE);

        #pragma unroll
        for (int s = 0; s < 4; s++) {
            unsigned af[4][4], bf[4][2];
            #pragma unroll
            for (int mi = 0; mi < 4; mi++) {
                const float* p = AsB + (wm * 64 + mi * 16 + lr) * AS_STRIDE + s * 8 + lc;
                af[mi][0] = f2tf32(p[0]);
                af[mi][1] = f2tf32(p[8 * AS_STRIDE]);
                af[mi][2] = f2tf32(p[4]);
                af[mi][3] = f2tf32(p[8 * AS_STRIDE + 4]);
            }
            #pragma unroll
            for (int ni = 0; ni < 4; ni++) {
                const float* p = BsB + (s * 8 + lc) * BS_STRIDE + wn * 32 + ni * 8 + lr;
                bf[ni][0] = f2tf32(p[0]);
                bf[ni][1] = f2tf32(p[4 * BS_STRIDE]);
            }
            #pragma unroll
            for (int mi = 0; mi < 4; mi++)
                #pragma unroll
                for (int ni = 0; ni < 4; ni++) {
                    asm volatile(
                        "mma.sync.aligned.m16n8k8.row.col.f32.tf32.tf32.f32 "
                        "{%0,%1,%2,%3},{%4,%5,%6,%7},{%8,%9},{%0,%1,%2,%3};\n"
                        : "+f"(acc[mi][ni][0]), "+f"(acc[mi][ni][1]),
                          "+f"(acc[mi][ni][2]), "+f"(acc[mi][ni][3])
                        : "r"(af[mi][0]), "r"(af[mi][1]), "r"(af[mi][2]), "r"(af[mi][3]),
                          "r"(bf[ni][0]), "r"(bf[ni][1]));
                }
        }
        __syncthreads();
    }

    #pragma unroll
    for (int mi = 0; mi < 4; mi++) {
        int r0r = m0 + wm * 64 + mi * 16 + lr;
        #pragma unroll
        for (int ni = 0; ni < 4; ni++) {
            int cb = n0 + wn * 32 + ni * 8 + 2 * lc;
            #pragma unroll
            for (int q = 0; q < 4; q++) {
                int r = r0r + (q >> 1) * 8;
                int c = cb + (q & 1);
                if (c < N) {
                    float v = acc[mi][ni][q];
                    if (epi == 1) {
                        v += bias[c];
                        v = (v > 20.f) ? v : log1pf(__expf(v));
                    } else if (epi == 2) {
                        v += bias[c] + resid[(size_t)r * N + c];
                    }
                    int cr = fC ? (r ^ (LSEQ - 1)) : r;
                    C[(size_t)cr * ldc + coff + c] = v;
                }
            }
        }
    }
}

// ---------------- causal depthwise conv (DC=4) + bias + SiLU ---------------
__global__ void conv_silu_kernel(const float* __restrict__ xr0, const float* __restrict__ xr1,
                                 const float* __restrict__ cw0, const float* __restrict__ cw1,
                                 const float* __restrict__ cb0, const float* __restrict__ cb1,
                                 float* __restrict__ xsc0, float* __restrict__ xsc1)
{
    int dir = blockIdx.y;
    const float* xr = dir ? xr1 : xr0;
    const float* cw = dir ? cw1 : cw0;
    const float* cb = dir ? cb1 : cb0;
    float* xsc = dir ? xsc1 : xsc0;

    int idx = blockIdx.x * 256 + threadIdx.x;
    int row = idx >> 9;
    int c   = idx & (DI - 1);
    int tau = row & (LSEQ - 1);
    const float* p = xr + (size_t)row * (2 * DI) + c;
    float w0 = cw[c * 4 + 0], w1 = cw[c * 4 + 1], w2 = cw[c * 4 + 2], w3 = cw[c * 4 + 3];
    float acc = cb[c];
    if (tau >= 3) acc = fmaf(p[-3 * 2 * DI], w0, acc);
    if (tau >= 2) acc = fmaf(p[-2 * 2 * DI], w1, acc);
    if (tau >= 1) acc = fmaf(p[-1 * 2 * DI], w2, acc);
    acc = fmaf(p[0], w3, acc);
    float sv = acc / (1.f + __expf(-acc));
    xsc[(size_t)row * DI + c] = sv;
}

// ---------------- chunked selective scan -----------------------------------
// p[n] = q^(n+1), log-depth
__device__ __forceinline__ void powers16(float q, float* p) {
    p[0] = q;        p[1] = q * q;     p[2] = p[1] * q;   p[3] = p[1] * p[1];
    p[4] = p[3] * q; p[5] = p[3] * p[1]; p[6] = p[3] * p[2]; p[7] = p[3] * p[3];
    p[8]  = p[7] * q;    p[9]  = p[7] * p[1]; p[10] = p[7] * p[2]; p[11] = p[7] * p[3];
    p[12] = p[7] * p[4]; p[13] = p[7] * p[5]; p[14] = p[7] * p[6]; p[15] = p[7] * p[7];
}

__device__ __forceinline__ bool load_a(const float* __restrict__ ALog, int d, float* a) {
    #pragma unroll
    for (int n = 0; n < 16; n++) a[n] = -__expf(ALog[d * 16 + n]);
    bool fast = true;
    float a1 = a[0];
    #pragma unroll
    for (int n = 1; n < 16; n++)
        fast = fast && (fabsf(a[n] - (n + 1) * a1) <= 1e-4f * fabsf((n + 1) * a1));
    return fast;
}

// Phase A: local scan per (dir,b,chunk,d). Writes local y, chunk-final h, sum(delta).
__global__ __launch_bounds__(128)
void scanA_kernel(const float* __restrict__ xdbl0, const float* __restrict__ xdbl1,
                  const float* __restrict__ delta0, const float* __restrict__ delta1,
                  const float* __restrict__ xsc0, const float* __restrict__ xsc1,
                  const float* __restrict__ ALog0, const float* __restrict__ ALog1,
                  float* __restrict__ y0, float* __restrict__ y1,
                  float* __restrict__ hfin, float* __restrict__ dSb)
{
    int zb  = blockIdx.z;             // dir*8 + b
    int dir = zb >> 3;
    const float* xdbl  = dir ? xdbl1  : xdbl0;
    const float* delta = dir ? delta1 : delta0;
    const float* xsc   = dir ? xsc1   : xsc0;
    const float* ALog  = dir ? ALog1  : ALog0;
    float* y           = dir ? y1     : y0;

    int ch  = blockIdx.y;
    int tid = threadIdx.x;
    int d   = blockIdx.x * 128 + tid;
    int b   = zb & 7;
    int base = b * LSEQ + ch * CH;

    __shared__ float sBC[CH][32];
    for (int i = tid; i < CH * 8; i += 128) {
        int tt = i >> 3, q = i & 7;
        *(float4*)&sBC[tt][q * 4] =
            *(const float4*)&xdbl[(size_t)(base + tt) * XDBLC + DTR + q * 4];
    }
    __syncthreads();

    float a[16];
    bool fast = load_a(ALog, d, a);
    float a1 = a[0];

    float h[16];
    #pragma unroll
    for (int n = 0; n < 16; n++) h[n] = 0.f;
    float S = 0.f;

    const float* dp = delta + (size_t)base * DI + d;
    const float* xp = xsc   + (size_t)base * DI + d;
    float* yp       = y     + (size_t)base * DI + d;

    if (fast) {
        #pragma unroll 2
        for (int t = 0; t < CH; t++) {
            float dlt = dp[(size_t)t * DI];
            float xv  = xp[(size_t)t * DI];
            S += dlt;
            float dx = dlt * xv;
            float p[16];
            powers16(__expf(dlt * a1), p);
            float yv = 0.f;
            #pragma unroll
            for (int n = 0; n < 16; n++) {
                h[n] = fmaf(p[n], h[n], dx * sBC[t][n]);
                yv   = fmaf(h[n], sBC[t][16 + n], yv);
            }
            yp[(size_t)t * DI] = yv;
        }
    } else {
        for (int t = 0; t < CH; t++) {
            float dlt = dp[(size_t)t * DI];
            float xv  = xp[(size_t)t * DI];
            S += dlt;
            float dx = dlt * xv;
            float yv = 0.f;
            #pragma unroll
            for (int n = 0; n < 16; n++) {
                float dA = __expf(dlt * a[n]);
                h[n] = fmaf(dA, h[n], dx * sBC[t][n]);
                yv   = fmaf(h[n], sBC[t][16 + n], yv);
            }
            yp[(size_t)t * DI] = yv;
        }
    }

    size_t cc = (size_t)(zb * NCH + ch);
    #pragma unroll
    for (int n = 0; n < 16; n++) hfin[cc * 8192 + n * 512 + d] = h[n];
    dSb[cc * 512 + d] = S;
}

// Phase B: sequential combine over chunks; rewrites hfin[c] with incoming state h_in(c).
__global__ void scanB_kernel(float* __restrict__ hfin, const float* __restrict__ dSb,
                             const float* __restrict__ ALog0, const float* __restrict__ ALog1)
{
    int idx = blockIdx.x * 256 + threadIdx.x;  // 0..8191
    int d  = idx & 511;
    int zb = idx >> 9;
    const float* ALog = (zb >> 3) ? ALog1 : ALog0;

    float a[16];
    bool fast = load_a(ALog, d, a);
    float a1 = a[0];

    float hin[16];
    #pragma unroll
    for (int n = 0; n < 16; n++) hin[n] = 0.f;

    for (int c = 0; c < NCH; c++) {
        size_t cc = (size_t)(zb * NCH + c);
        float S = dSb[cc * 512 + d];
        float P[16];
        if (fast) {
            powers16(__expf(S * a1), P);
        } else {
            #pragma unroll
            for (int n = 0; n < 16; n++) P[n] = __expf(S * a[n]);
        }
        #pragma unroll
        for (int n = 0; n < 16; n++) {
            float hf = hfin[cc * 8192 + n * 512 + d];
            hfin[cc * 8192 + n * 512 + d] = hin[n];
            hin[n] = fmaf(P[n], hin[n], hf);
        }
    }
}

// Phase C: cross-chunk correction + D*x + silu(res) gating. y in-place.
__global__ __launch_bounds__(128)
void scanC_kernel(const float* __restrict__ xdbl0, const float* __restrict__ xdbl1,
                  const float* __restrict__ delta0, const float* __restrict__ delta1,
                  const float* __restrict__ xsc0, const float* __restrict__ xsc1,
                  const float* __restrict__ xr0, const float* __restrict__ xr1,
                  const float* __restrict__ ALog0, const float* __restrict__ ALog1,
                  const float* __restrict__ Dp0, const float* __restrict__ Dp1,
                  float* __restrict__ y0, float* __restrict__ y1,
                  const float* __restrict__ hfin)
{
    int zb  = blockIdx.z;
    int dir = zb >> 3;
    const float* xdbl  = dir ? xdbl1  : xdbl0;
    const float* delta = dir ? delta1 : delta0;
    const float* xsc   = dir ? xsc1   : xsc0;
    const float* xr    = dir ? xr1    : xr0;
    const float* ALog  = dir ? ALog1  : ALog0;
    const float* Dp    = dir ? Dp1    : Dp0;
    float* y           = dir ? y1     : y0;

    int ch  = blockIdx.y;
    int tid = threadIdx.x;
    int d   = blockIdx.x * 128 + tid;
    int b   = zb & 7;
    int base = b * LSEQ + ch * CH;

    __shared__ float sC[CH][16];
    for (int i = tid; i < CH * 4; i += 128) {
        int tt = i >> 2, q = i & 3;
        *(float4*)&sC[tt][q * 4] =
            *(const float4*)&xdbl[(size_t)(base + tt) * XDBLC + DTR + DS + q * 4];
    }
    __syncthreads();

    float a[16];
    bool fast = load_a(ALog, d, a);
    float a1 = a[0];
    float Dv = Dp[d];

    size_t cc = (size_t)(zb * NCH + ch);
    float w[16];
    bool zero = true;
    #pragma unroll
    for (int n = 0; n < 16; n++) {
        w[n] = hfin[cc * 8192 + n * 512 + d];
        zero = zero && (w[n] == 0.f);
    }

    const float* dp = delta + (size_t)base * DI + d;
    const float* xp = xsc   + (size_t)base * DI + d;
    const float* rp = xr    + (size_t)base * (2 * DI) + DI + d;
    float* yp       = y     + (size_t)base * DI + d;

    if (zero) {
        #pragma unroll 4
        for (int t = 0; t < CH; t++) {
            float xv  = xp[(size_t)t * DI];
            float res = rp[(size_t)t * (2 * DI)];
            float yl  = yp[(size_t)t * DI];
            float sres = res / (1.f + __expf(-res));
            yp[(size_t)t * DI] = (yl + Dv * xv) * sres;
        }
    } else if (fast) {
        float r = 1.f;
        #pragma unroll 2
        for (int t = 0; t < CH; t++) {
            float dlt = dp[(size_t)t * DI];
            float xv  = xp[(size_t)t * DI];
            float res = rp[(size_t)t * (2 * DI)];
            float yl  = yp[(size_t)t * DI];
            r *= __expf(dlt * a1);
            float p[16];
            powers16(r, p);
            float corr = 0.f;
            #pragma unroll
            for (int n = 0; n < 16; n++)
                corr = fmaf(w[n] * p[n], sC[t][n], corr);
            float sres = res / (1.f + __expf(-res));
            yp[(size_t)t * DI] = (yl + corr + Dv * xv) * sres;
        }
    } else {
        float S = 0.f;
        for (int t = 0; t < CH; t++) {
            float dlt = dp[(size_t)t * DI];
            float xv  = xp[(size_t)t * DI];
            float res = rp[(size_t)t * (2 * DI)];
            float yl  = yp[(size_t)t * DI];
            S += dlt;
            float corr = 0.f;
            #pragma unroll
            for (int n = 0; n < 16; n++)
                corr = fmaf(w[n] * __expf(S * a[n]), sC[t][n], corr);
            float sres = res / (1.f + __expf(-res));
            yp[(size_t)t * DI] = (yl + corr + Dv * xv) * sres;
        }
    }
}

// ---------------- launcher -------------------------------------------------
extern "C" void kernel_launch(void* const* d_in, const int* in_sizes, int n_in,
                              void* d_out, int out_size)
{
    const float* x      = (const float*)d_in[0];
    const float* norm_g = (const float*)d_in[1];
    const float* norm_b = (const float*)d_in[2];
    const float* inW[2]   = {(const float*)d_in[3],  (const float*)d_in[12]};
    const float* convW[2] = {(const float*)d_in[4],  (const float*)d_in[13]};
    const float* convB[2] = {(const float*)d_in[5],  (const float*)d_in[14]};
    const float* xW[2]    = {(const float*)d_in[6],  (const float*)d_in[15]};
    const float* dtW[2]   = {(const float*)d_in[7],  (const float*)d_in[16]};
    const float* dtB[2]   = {(const float*)d_in[8],  (const float*)d_in[17]};
    const float* ALog[2]  = {(const float*)d_in[9],  (const float*)d_in[18]};
    const float* Dp[2]    = {(const float*)d_in[10], (const float*)d_in[19]};
    const float* outW[2]  = {(const float*)d_in[11], (const float*)d_in[20]};
    const float* fusW = (const float*)d_in[21];
    const float* fusB = (const float*)d_in[22];
    float* out = (float*)d_out;

    float* base = nullptr;
    cudaGetSymbolAddress((void**)&base, g_buf);
    float* xn        = base + OFF_XN;
    float* xr_[2]    = {base + OFF_XR,    base + OFF_XR    + (size_t)BL * 2 * DI};
    float* xsc_[2]   = {base + OFF_XSC,   base + OFF_XSC   + (size_t)BL * DI};
    float* xdbl_[2]  = {base + OFF_XDBL,  base + OFF_XDBL  + (size_t)BL * XDBLC};
    float* delta_[2] = {base + OFF_DELTA, base + OFF_DELTA + (size_t)BL * DI};
    float* y_[2]     = {base + OFF_Y,     base + OFF_Y     + (size_t)BL * DI};
    float* cat_      = base + OFF_CAT;
    float* hfin      = base + OFF_HF;
    float* dSb       = base + OFF_DS;

    static bool attr_set = false;
    if (!attr_set) {
        cudaFuncSetAttribute(mma_gemm, cudaFuncAttributeMaxDynamicSharedMemorySize, SMEM_BYTES);
        attr_set = true;
    }

    // 1) LayerNorm
    ln_kernel<<<BL, 256>>>(x, norm_g, norm_b, xn);

    // 2) in_proj, both dirs (flip A rows for backward)
    mma_gemm<<<dim3(BL / 128, 8, 2), 256, SMEM_BYTES>>>(
        xn, xn, DM, 1,
        inW[0], inW[1], 2 * DI,
        xr_[0], xr_[1], 2 * DI, 0, 0,
        2 * DI, DM, 0, nullptr, nullptr, nullptr);

    // 3) causal dw-conv + silu, both dirs
    conv_silu_kernel<<<dim3((BL * DI) / 256, 2), 256>>>(
        xr_[0], xr_[1], convW[0], convW[1], convB[0], convB[1], xsc_[0], xsc_[1]);

    // 4) x_proj -> [dlt | B | C], both dirs
    mma_gemm<<<dim3(BL / 128, 1, 2), 256, SMEM_BYTES>>>(
        xsc_[0], xsc_[1], DI, 0,
        xW[0], xW[1], XDBLC,
        xdbl_[0], xdbl_[1], XDBLC, 0, 0,
        XDBLC, DI, 0, nullptr, nullptr, nullptr);

    // 5) delta = softplus(dlt @ dtW + dtB), both dirs
    mma_gemm<<<dim3(BL / 128, 4, 2), 256, SMEM_BYTES>>>(
        xdbl_[0], xdbl_[1], XDBLC, 0,
        dtW[0], dtW[1], DI,
        delta_[0], delta_[1], DI, 0, 0,
        DI, DTR, 1, dtB[0], dtB[1], nullptr);

    // 6) chunked scan: local -> combine -> correct+gate
    scanA_kernel<<<dim3(DI / 128, NCH, 16), 128>>>(
        xdbl_[0], xdbl_[1], delta_[0], delta_[1], xsc_[0], xsc_[1],
        ALog[0], ALog[1], y_[0], y_[1], hfin, dSb);
    scanB_kernel<<<32, 256>>>(hfin, dSb, ALog[0], ALog[1]);
    scanC_kernel<<<dim3(DI / 128, NCH, 16), 128>>>(
        xdbl_[0], xdbl_[1], delta_[0], delta_[1], xsc_[0], xsc_[1],
        xr_[0], xr_[1], ALog[0], ALog[1], Dp[0], Dp[1], y_[0], y_[1], hfin);

    // 7) out_proj into concat buffer (unflip rows for backward)
    mma_gemm<<<dim3(BL / 128, 2, 2), 256, SMEM_BYTES>>>(
        y_[0], y_[1], DI, 0,
        outW[0], outW[1], DM,
        cat_, cat_, 512, 1, DM,
        DM, DI, 0, nullptr, nullptr, nullptr);

    // 8) fuse: out = x + cat @ fusW + fusB
    mma_gemm<<<dim3(BL / 128, 2, 1), 256, SMEM_BYTES>>>(
        cat_, cat_, 512, 0,
        fusW, fusW, DM,
        out, out, DM, 0, 0,
        DM, 512, 2, fusB, fusB, x);
}

// round 4
// speedup vs baseline: 5.4249x; 1.0252x over previous
#include <cuda_runtime.h>
#include <cstdint>

#define BATCH 8
#define LSEQ  1024
#define DM    256
#define DS    16
#define DC    4
#define DI    512
#define DTR   16
#define BL    (BATCH * LSEQ)   // 8192
#define XDBLC (DTR + 2 * DS)   // 48
#define CH    128
#define NCH   (LSEQ / CH)      // 8

// ---------------- scratch (single static device buffer; no allocations) ---
static const size_t OFF_XN    = 0;
static const size_t OFF_XR    = OFF_XN    + (size_t)BL * DM;
static const size_t OFF_XSC   = OFF_XR    + (size_t)2 * BL * 2 * DI;
static const size_t OFF_XDBL  = OFF_XSC   + (size_t)2 * BL * DI;
static const size_t OFF_DELTA = OFF_XDBL  + (size_t)2 * BL * XDBLC;
static const size_t OFF_Y     = OFF_DELTA + (size_t)2 * BL * DI;
static const size_t OFF_WC    = OFF_Y     + (size_t)2 * BL * DI;     // combined weights 1024x256
static const size_t OFF_HF    = OFF_WC    + (size_t)1024 * 256;
static const size_t OFF_DS    = OFF_HF    + (size_t)2 * 8 * NCH * 16 * 512;
static const size_t TOTAL_F   = OFF_DS    + (size_t)2 * 8 * NCH * 512;

__device__ float g_buf[TOTAL_F];

// ---------------- LayerNorm ------------------------------------------------
__global__ void ln_kernel(const float* __restrict__ x,
                          const float* __restrict__ g,
                          const float* __restrict__ b,
                          float* __restrict__ xn)
{
    int m = blockIdx.x;
    int t = threadIdx.x;
    float v = x[(size_t)m * DM + t];
    float s = v, s2 = v * v;
    #pragma unroll
    for (int o = 16; o; o >>= 1) {
        s  += __shfl_xor_sync(0xffffffffu, s,  o);
        s2 += __shfl_xor_sync(0xffffffffu, s2, o);
    }
    __shared__ float ws[8], ws2[8];
    int w = t >> 5, l = t & 31;
    if (l == 0) { ws[w] = s; ws2[w] = s2; }
    __syncthreads();
    float S = 0.f, S2 = 0.f;
    #pragma unroll
    for (int i = 0; i < 8; i++) { S += ws[i]; S2 += ws2[i]; }
    float mu  = S * (1.0f / DM);
    float var = S2 * (1.0f / DM) - mu * mu;
    float r = rsqrtf(var + 1e-5f);
    xn[(size_t)m * DM + t] = (v - mu) * r * g[t] + b[t];
}

// ---------------- tf32 tensor-core GEMM ------------------------------------
// 128x128x32 tiles, 3-stage cp.async ring, 256 threads (8 warps, 2x4),
// warp tile 64x32. No cvt: raw f32 fed to tf32 mma (HW truncates).
// flipMode: 0 none; 1 flip A rows when z==1; 2 dual-A (K split at 512:
//           k<512 reads A0[m], k>=512 reads A1[m^1023]).
// epi: 0 none; 1 softplus(v+bias[c]); 2 v+bias[c]+resid[r*N+c].

#define AS_STRIDE 36
#define BS_STRIDE 136
#define STAGES 3
#define SMEM_BYTES (STAGES * (128*AS_STRIDE + 32*BS_STRIDE) * 4)

__device__ __forceinline__ unsigned cvta_s(const void* p) {
    return (unsigned)__cvta_generic_to_shared(p);
}
__device__ __forceinline__ void cp16(unsigned dst, const void* src, int srcbytes) {
    asm volatile("cp.async.cg.shared.global [%0], [%1], 16, %2;\n"
                 :: "r"(dst), "l"(src), "r"(srcbytes));
}

__global__ __launch_bounds__(256)
void mma_gemm(const float* __restrict__ A0, const float* __restrict__ A1, int lda, int flipMode,
              const float* __restrict__ W0, const float* __restrict__ W1, int ldw,
              float* __restrict__ C0, float* __restrict__ C1, int ldc, int flipC, int coffz,
              int N, int K, int epi,
              const float* __restrict__ bias0, const float* __restrict__ bias1,
              const float* __restrict__ resid)
{
    extern __shared__ float smem[];
    float* As = smem;                                  // [STAGES][128][AS_STRIDE]
    float* Bs = smem + STAGES * 128 * AS_STRIDE;       // [STAGES][32][BS_STRIDE]

    const int z = blockIdx.z;
    const float* A = z ? A1 : A0;
    const float* W = z ? W1 : W0;
    float*       C = z ? C1 : C0;
    const float* bias = z ? bias1 : bias0;
    const bool dual = (flipMode == 2);
    const int fA = (flipMode == 1 && z);
    const int fC = (flipC && z);
    const int coff = coffz * z;

    const int tid = threadIdx.x;
    const int m0 = blockIdx.x * 128;
    const int n0 = blockIdx.y * 128;

    const int ar  = tid >> 1;
    const int akc = (tid & 1) * 16;
    int gm = m0 + ar;
    if (fA) gm ^= (LSEQ - 1);
    const float* A0row = A + (size_t)gm * lda;
    const float* A1row = dual ? (A1 + (size_t)(gm ^ (LSEQ - 1)) * lda) : nullptr;

    const int bkr = tid >> 3;
    const int bnc = (tid & 7) * 16;

    const int wid = tid >> 5, lane = tid & 31;
    const int wm = wid & 1, wn = wid >> 1;
    const int lr = lane >> 2, lc = lane & 3;

    float acc[4][4][4];
    #pragma unroll
    for (int mi = 0; mi < 4; mi++)
        #pragma unroll
        for (int ni = 0; ni < 4; ni++)
            #pragma unroll
            for (int q = 0; q < 4; q++) acc[mi][ni][q] = 0.f;

    const int nk = (K + 31) >> 5;

    auto loadA = [&](int kk, int buf) {
        float* dst = As + buf * (128 * AS_STRIDE) + ar * AS_STRIDE + akc;
        #pragma unroll
        for (int j = 0; j < 4; j++) {
            int kg = kk + akc + j * 4;
            int sb = (kg < K) ? 16 : 0;
            const float* src;
            if (dual && kg >= 512) src = A1row + (kg - 512);
            else                   src = A0row + (sb ? kg : 0);
            cp16(cvta_s(dst + j * 4), src, sb);
        }
    };
    auto loadB = [&](int kk, int buf) {
        int kg = kk + bkr;
        int inK = (kg < K);
        const float* srow = W + (size_t)(inK ? kg : 0) * ldw;
        float* dst = Bs + buf * (32 * BS_STRIDE) + bkr * BS_STRIDE + bnc;
        #pragma unroll
        for (int j = 0; j < 4; j++) {
            int gn = n0 + bnc + j * 4;
            int sb = (inK && gn < N) ? 16 : 0;
            cp16(cvta_s(dst + j * 4), srow + (sb ? gn : 0), sb);
        }
    };

    // prologue: stage 0 and 1
    loadA(0, 0); loadB(0, 0);
    asm volatile("cp.async.commit_group;\n");
    loadA(32, 1); loadB(32, 1);
    asm volatile("cp.async.commit_group;\n");

    int buf = 0;
    for (int t = 0; t < nk; t++) {
        asm volatile("cp.async.wait_group %0;\n" :: "n"(STAGES - 2));
        __syncthreads();

        // prefetch stage t+2 into the buffer freed at iteration t-1
        if (t + STAGES - 1 < nk) {
            int nb = buf + (STAGES - 1); if (nb >= STAGES) nb -= STAGES;
            loadA((t + STAGES - 1) << 5, nb);
            loadB((t + STAGES - 1) << 5, nb);
        }
        asm volatile("cp.async.commit_group;\n");

        const float* AsB = As + buf * (128 * AS_STRIDE);
        const float* BsB = Bs + buf * (32 * BS_STRIDE);

        #pragma unroll
        for (int s = 0; s < 4; s++) {
            unsigned af[4][4], bf[4][2];
            #pragma unroll
            for (int mi = 0; mi < 4; mi++) {
                const float* p = AsB + (wm * 64 + mi * 16 + lr) * AS_STRIDE + s * 8 + lc;
                af[mi][0] = __float_as_uint(p[0]);
                af[mi][1] = __float_as_uint(p[8 * AS_STRIDE]);
                af[mi][2] = __float_as_uint(p[4]);
                af[mi][3] = __float_as_uint(p[8 * AS_STRIDE + 4]);
            }
            #pragma unroll
            for (int ni = 0; ni < 4; ni++) {
                const float* p = BsB + (s * 8 + lc) * BS_STRIDE + wn * 32 + ni * 8 + lr;
                bf[ni][0] = __float_as_uint(p[0]);
                bf[ni][1] = __float_as_uint(p[4 * BS_STRIDE]);
            }
            #pragma unroll
            for (int mi = 0; mi < 4; mi++)
                #pragma unroll
                for (int ni = 0; ni < 4; ni++) {
                    asm volatile(
                        "mma.sync.aligned.m16n8k8.row.col.f32.tf32.tf32.f32 "
                        "{%0,%1,%2,%3},{%4,%5,%6,%7},{%8,%9},{%0,%1,%2,%3};\n"
                        : "+f"(acc[mi][ni][0]), "+f"(acc[mi][ni][1]),
                          "+f"(acc[mi][ni][2]), "+f"(acc[mi][ni][3])
                        : "r"(af[mi][0]), "r"(af[mi][1]), "r"(af[mi][2]), "r"(af[mi][3]),
                          "r"(bf[ni][0]), "r"(bf[ni][1]));
                }
        }
        buf++; if (buf >= STAGES) buf = 0;
    }

    #pragma unroll
    for (int mi = 0; mi < 4; mi++) {
        int r0r = m0 + wm * 64 + mi * 16 + lr;
        #pragma unroll
        for (int ni = 0; ni < 4; ni++) {
            int cb = n0 + wn * 32 + ni * 8 + 2 * lc;
            #pragma unroll
            for (int q = 0; q < 4; q++) {
                int r = r0r + (q >> 1) * 8;
                int c = cb + (q & 1);
                if (c < N) {
                    float v = acc[mi][ni][q];
                    if (epi == 1) {
                        v += bias[c];
                        v = (v > 20.f) ? v : log1pf(__expf(v));
                    } else if (epi == 2) {
                        v += bias[c] + resid[(size_t)r * N + c];
                    }
                    int cr = fC ? (r ^ (LSEQ - 1)) : r;
                    C[(size_t)cr * ldc + coff + c] = v;
                }
            }
        }
    }
}

// ---------------- causal depthwise conv (DC=4) + bias + SiLU ---------------
__global__ void conv_silu_kernel(const float* __restrict__ xr0, const float* __restrict__ xr1,
                                 const float* __restrict__ cw0, const float* __restrict__ cw1,
                                 const float* __restrict__ cb0, const float* __restrict__ cb1,
                                 float* __restrict__ xsc0, float* __restrict__ xsc1)
{
    int dir = blockIdx.y;
    const float* xr = dir ? xr1 : xr0;
    const float* cw = dir ? cw1 : cw0;
    const float* cb = dir ? cb1 : cb0;
    float* xsc = dir ? xsc1 : xsc0;

    int idx = blockIdx.x * 256 + threadIdx.x;
    int row = idx >> 9;
    int c   = idx & (DI - 1);
    int tau = row & (LSEQ - 1);
    const float* p = xr + (size_t)row * (2 * DI) + c;
    float w0 = cw[c * 4 + 0], w1 = cw[c * 4 + 1], w2 = cw[c * 4 + 2], w3 = cw[c * 4 + 3];
    float acc = cb[c];
    if (tau >= 3) acc = fmaf(p[-3 * 2 * DI], w0, acc);
    if (tau >= 2) acc = fmaf(p[-2 * 2 * DI], w1, acc);
    if (tau >= 1) acc = fmaf(p[-1 * 2 * DI], w2, acc);
    acc = fmaf(p[0], w3, acc);
    float sv = acc / (1.f + __expf(-acc));
    xsc[(size_t)row * DI + c] = sv;
}

// ---------------- chunked selective scan -----------------------------------
__device__ __forceinline__ void powers16(float q, float* p) {
    p[0] = q;        p[1] = q * q;     p[2] = p[1] * q;   p[3] = p[1] * p[1];
    p[4] = p[3] * q; p[5] = p[3] * p[1]; p[6] = p[3] * p[2]; p[7] = p[3] * p[3];
    p[8]  = p[7] * q;    p[9]  = p[7] * p[1]; p[10] = p[7] * p[2]; p[11] = p[7] * p[3];
    p[12] = p[7] * p[4]; p[13] = p[7] * p[5]; p[14] = p[7] * p[6]; p[15] = p[7] * p[7];
}

__device__ __forceinline__ bool load_a(const float* __restrict__ ALog, int d, float* a) {
    #pragma unroll
    for (int n = 0; n < 16; n++) a[n] = -__expf(ALog[d * 16 + n]);
    bool fast = true;
    float a1 = a[0];
    #pragma unroll
    for (int n = 1; n < 16; n++)
        fast = fast && (fabsf(a[n] - (n + 1) * a1) <= 1e-4f * fabsf((n + 1) * a1));
    return fast;
}

__global__ __launch_bounds__(128)
void scanA_kernel(const float* __restrict__ xdbl0, const float* __restrict__ xdbl1,
                  const float* __restrict__ delta0, const float* __restrict__ delta1,
                  const float* __restrict__ xsc0, const float* __restrict__ xsc1,
                  const float* __restrict__ ALog0, const float* __restrict__ ALog1,
                  float* __restrict__ y0, float* __restrict__ y1,
                  float* __restrict__ hfin, float* __restrict__ dSb)
{
    int zb  = blockIdx.z;
    int dir = zb >> 3;
    const float* xdbl  = dir ? xdbl1  : xdbl0;
    const float* delta = dir ? delta1 : delta0;
    const float* xsc   = dir ? xsc1   : xsc0;
    const float* ALog  = dir ? ALog1  : ALog0;
    float* y           = dir ? y1     : y0;

    int ch  = blockIdx.y;
    int tid = threadIdx.x;
    int d   = blockIdx.x * 128 + tid;
    int b   = zb & 7;
    int base = b * LSEQ + ch * CH;

    __shared__ float sBC[CH][32];
    for (int i = tid; i < CH * 8; i += 128) {
        int tt = i >> 3, q = i & 7;
        *(float4*)&sBC[tt][q * 4] =
            *(const float4*)&xdbl[(size_t)(base + tt) * XDBLC + DTR + q * 4];
    }
    __syncthreads();

    float a[16];
    bool fast = load_a(ALog, d, a);
    float a1 = a[0];

    float h[16];
    #pragma unroll
    for (int n = 0; n < 16; n++) h[n] = 0.f;
    float S = 0.f;

    const float* dp = delta + (size_t)base * DI + d;
    const float* xp = xsc   + (size_t)base * DI + d;
    float* yp       = y     + (size_t)base * DI + d;

    if (fast) {
        #pragma unroll 2
        for (int t = 0; t < CH; t++) {
            float dlt = dp[(size_t)t * DI];
            float xv  = xp[(size_t)t * DI];
            S += dlt;
            float dx = dlt * xv;
            float p[16];
            powers16(__expf(dlt * a1), p);
            float yv = 0.f;
            #pragma unroll
            for (int n = 0; n < 16; n++) {
                h[n] = fmaf(p[n], h[n], dx * sBC[t][n]);
                yv   = fmaf(h[n], sBC[t][16 + n], yv);
            }
            yp[(size_t)t * DI] = yv;
        }
    } else {
        for (int t = 0; t < CH; t++) {
            float dlt = dp[(size_t)t * DI];
            float xv  = xp[(size_t)t * DI];
            S += dlt;
            float dx = dlt * xv;
            float yv = 0.f;
            #pragma unroll
            for (int n = 0; n < 16; n++) {
                float dA = __expf(dlt * a[n]);
                h[n] = fmaf(dA, h[n], dx * sBC[t][n]);
                yv   = fmaf(h[n], sBC[t][16 + n], yv);
            }
            yp[(size_t)t * DI] = yv;
        }
    }

    size_t cc = (size_t)(zb * NCH + ch);
    #pragma unroll
    for (int n = 0; n < 16; n++) hfin[cc * 8192 + n * 512 + d] = h[n];
    dSb[cc * 512 + d] = S;
}

__global__ void scanB_kernel(float* __restrict__ hfin, const float* __restrict__ dSb,
                             const float* __restrict__ ALog0, const float* __restrict__ ALog1)
{
    int idx = blockIdx.x * 256 + threadIdx.x;
    int d  = idx & 511;
    int zb = idx >> 9;
    const float* ALog = (zb >> 3) ? ALog1 : ALog0;

    float a[16];
    bool fast = load_a(ALog, d, a);
    float a1 = a[0];

    float hin[16];
    #pragma unroll
    for (int n = 0; n < 16; n++) hin[n] = 0.f;

    for (int c = 0; c < NCH; c++) {
        size_t cc = (size_t)(zb * NCH + c);
        float S = dSb[cc * 512 + d];
        float P[16];
        if (fast) {
            powers16(__expf(S * a1), P);
        } else {
            #pragma unroll
            for (int n = 0; n < 16; n++) P[n] = __expf(S * a[n]);
        }
        #pragma unroll
        for (int n = 0; n < 16; n++) {
            float hf = hfin[cc * 8192 + n * 512 + d];
            hfin[cc * 8192 + n * 512 + d] = hin[n];
            hin[n] = fmaf(P[n], hin[n], hf);
        }
    }
}

__global__ __launch_bounds__(128)
void scanC_kernel(const float* __restrict__ xdbl0, const float* __restrict__ xdbl1,
                  const float* __restrict__ delta0, const float* __restrict__ delta1,
                  const float* __restrict__ xsc0, const float* __restrict__ xsc1,
                  const float* __restrict__ xr0, const float* __restrict__ xr1,
                  const float* __restrict__ ALog0, const float* __restrict__ ALog1,
                  const float* __restrict__ Dp0, const float* __restrict__ Dp1,
                  float* __restrict__ y0, float* __restrict__ y1,
                  const float* __restrict__ hfin)
{
    int zb  = blockIdx.z;
    int dir = zb >> 3;
    const float* xdbl  = dir ? xdbl1  : xdbl0;
    const float* delta = dir ? delta1 : delta0;
    const float* xsc   = dir ? xsc1   : xsc0;
    const float* xr    = dir ? xr1    : xr0;
    const float* ALog  = dir ? ALog1  : ALog0;
    const float* Dp    = dir ? Dp1    : Dp0;
    float* y           = dir ? y1     : y0;

    int ch  = blockIdx.y;
    int tid = threadIdx.x;
    int d   = blockIdx.x * 128 + tid;
    int b   = zb & 7;
    int base = b * LSEQ + ch * CH;

    __shared__ float sC[CH][16];
    for (int i = tid; i < CH * 4; i += 128) {
        int tt = i >> 2, q = i & 3;
        *(float4*)&sC[tt][q * 4] =
            *(const float4*)&xdbl[(size_t)(base + tt) * XDBLC + DTR + DS + q * 4];
    }
    __syncthreads();

    float a[16];
    bool fast = load_a(ALog, d, a);
    float a1 = a[0];
    float Dv = Dp[d];

    size_t cc = (size_t)(zb * NCH + ch);
    float w[16];
    bool zero = true;
    #pragma unroll
    for (int n = 0; n < 16; n++) {
        w[n] = hfin[cc * 8192 + n * 512 + d];
        zero = zero && (w[n] == 0.f);
    }

    const float* dp = delta + (size_t)base * DI + d;
    const float* xp = xsc   + (size_t)base * DI + d;
    const float* rp = xr    + (size_t)base * (2 * DI) + DI + d;
    float* yp       = y     + (size_t)base * DI + d;

    if (zero) {
        #pragma unroll 4
        for (int t = 0; t < CH; t++) {
            float xv  = xp[(size_t)t * DI];
            float res = rp[(size_t)t * (2 * DI)];
            float yl  = yp[(size_t)t * DI];
            float sres = res / (1.f + __expf(-res));
            yp[(size_t)t * DI] = (yl + Dv * xv) * sres;
        }
    } else if (fast) {
        float r = 1.f;
        #pragma unroll 2
        for (int t = 0; t < CH; t++) {
            float dlt = dp[(size_t)t * DI];
            float xv  = xp[(size_t)t * DI];
            float res = rp[(size_t)t * (2 * DI)];
            float yl  = yp[(size_t)t * DI];
            r *= __expf(dlt * a1);
            float p[16];
            powers16(r, p);
            float corr = 0.f;
            #pragma unroll
            for (int n = 0; n < 16; n++)
                corr = fmaf(w[n] * p[n], sC[t][n], corr);
            float sres = res / (1.f + __expf(-res));
            yp[(size_t)t * DI] = (yl + corr + Dv * xv) * sres;
        }
    } else {
        float S = 0.f;
        for (int t = 0; t < CH; t++) {
            float dlt = dp[(size_t)t * DI];
            float xv  = xp[(size_t)t * DI];
            float res = rp[(size_t)t * (2 * DI)];
            float yl  = yp[(size_t)t * DI];
            S += dlt;
            float corr = 0.f;
            #pragma unroll
            for (int n = 0; n < 16; n++)
                corr = fmaf(w[n] * __expf(S * a[n]), sC[t][n], corr);
            float sres = res / (1.f + __expf(-res));
            yp[(size_t)t * DI] = (yl + corr + Dv * xv) * sres;
        }
    }
}

// ---------------- launcher -------------------------------------------------
extern "C" void kernel_launch(void* const* d_in, const int* in_sizes, int n_in,
                              void* d_out, int out_size)
{
    const float* x      = (const float*)d_in[0];
    const float* norm_g = (const float*)d_in[1];
    const float* norm_b = (const float*)d_in[2];
    const float* inW[2]   = {(const float*)d_in[3],  (const float*)d_in[12]};
    const float* convW[2] = {(const float*)d_in[4],  (const float*)d_in[13]};
    const float* convB[2] = {(const float*)d_in[5],  (const float*)d_in[14]};
    const float* xW[2]    = {(const float*)d_in[6],  (const float*)d_in[15]};
    const float* dtW[2]   = {(const float*)d_in[7],  (const float*)d_in[16]};
    const float* dtB[2]   = {(const float*)d_in[8],  (const float*)d_in[17]};
    const float* ALog[2]  = {(const float*)d_in[9],  (const float*)d_in[18]};
    const float* Dp[2]    = {(const float*)d_in[10], (const float*)d_in[19]};
    const float* outW[2]  = {(const float*)d_in[11], (const float*)d_in[20]};
    const float* fusW = (const float*)d_in[21];
    const float* fusB = (const float*)d_in[22];
    float* out = (float*)d_out;

    float* base = nullptr;
    cudaGetSymbolAddress((void**)&base, g_buf);
    float* xn        = base + OFF_XN;
    float* xr_[2]    = {base + OFF_XR,    base + OFF_XR    + (size_t)BL * 2 * DI};
    float* xsc_[2]   = {base + OFF_XSC,   base + OFF_XSC   + (size_t)BL * DI};
    float* xdbl_[2]  = {base + OFF_XDBL,  base + OFF_XDBL  + (size_t)BL * XDBLC};
    float* delta_[2] = {base + OFF_DELTA, base + OFF_DELTA + (size_t)BL * DI};
    float* y_[2]     = {base + OFF_Y,     base + OFF_Y     + (size_t)BL * DI};
    float* Wcomb     = base + OFF_WC;
    float* hfin      = base + OFF_HF;
    float* dSb       = base + OFF_DS;

    static bool attr_set = false;
    if (!attr_set) {
        cudaFuncSetAttribute(mma_gemm, cudaFuncAttributeMaxDynamicSharedMemorySize, SMEM_BYTES);
        attr_set = true;
    }

    // 0) combined out+fuse weights: Cf = outW_f @ fusW_top, Cb = outW_b @ fusW_bot
    mma_gemm<<<dim3(4, 2, 2), 256, SMEM_BYTES>>>(
        outW[0], outW[1], DM, 0,
        fusW, fusW + (size_t)DM * DM, DM,
        Wcomb, Wcomb + (size_t)512 * DM, DM, 0, 0,
        DM, DM, 0, nullptr, nullptr, nullptr);

    // 1) LayerNorm
    ln_kernel<<<BL, 256>>>(x, norm_g, norm_b, xn);

    // 2) in_proj, both dirs (flip A rows for backward)
    mma_gemm<<<dim3(BL / 128, 8, 2), 256, SMEM_BYTES>>>(
        xn, xn, DM, 1,
        inW[0], inW[1], 2 * DI,
        xr_[0], xr_[1], 2 * DI, 0, 0,
        2 * DI, DM, 0, nullptr, nullptr, nullptr);

    // 3) causal dw-conv + silu, both dirs
    conv_silu_kernel<<<dim3((BL * DI) / 256, 2), 256>>>(
        xr_[0], xr_[1], convW[0], convW[1], convB[0], convB[1], xsc_[0], xsc_[1]);

    // 4) x_proj -> [dlt | B | C], both dirs
    mma_gemm<<<dim3(BL / 128, 1, 2), 256, SMEM_BYTES>>>(
        xsc_[0], xsc_[1], DI, 0,
        xW[0], xW[1], XDBLC,
        xdbl_[0], xdbl_[1], XDBLC, 0, 0,
        XDBLC, DI, 0, nullptr, nullptr, nullptr);

    // 5) delta = softplus(dlt @ dtW + dtB), both dirs
    mma_gemm<<<dim3(BL / 128, 4, 2), 256, SMEM_BYTES>>>(
        xdbl_[0], xdbl_[1], XDBLC, 0,
        dtW[0], dtW[1], DI,
        delta_[0], delta_[1], DI, 0, 0,
        DI, DTR, 1, dtB[0], dtB[1], nullptr);

    // 6) chunked scan: local -> combine -> correct+gate
    scanA_kernel<<<dim3(DI / 128, NCH, 16), 128>>>(
        xdbl_[0], xdbl_[1], delta_[0], delta_[1], xsc_[0], xsc_[1],
        ALog[0], ALog[1], y_[0], y_[1], hfin, dSb);
    scanB_kernel<<<32, 256>>>(hfin, dSb, ALog[0], ALog[1]);
    scanC_kernel<<<dim3(DI / 128, NCH, 16), 128>>>(
        xdbl_[0], xdbl_[1], delta_[0], delta_[1], xsc_[0], xsc_[1],
        xr_[0], xr_[1], ALog[0], ALog[1], Dp[0], Dp[1], y_[0], y_[1], hfin);

    // 7) combined out_proj + fuse + residual (dual-A, K=1024):
    //    out[m] = x[m] + fusB + y_f[m] @ Cf + y_b[m^1023] @ Cb
    mma_gemm<<<dim3(BL / 128, 2, 1), 256, SMEM_BYTES>>>(
        y_[0], y_[1], DI, 2,
        Wcomb, Wcomb, DM,
        out, out, DM, 0, 0,
        DM, 1024, 2, fusB, fusB, x);
}